// round 2
// baseline (speedup 1.0000x reference)
#include <cuda_runtime.h>
#include <cstdint>

#define NB 256
#define NQ 1000
#define NC 80
#define TOPK 300
#define NPAD 1024
#define T1 256          // kernel-1 block size (8 warps)
#define T2 512          // kernel-2 block size

typedef unsigned long long ull;

// per-(batch,query) packed keys: [ordered score 32b | (1023-q) 10b | label 10b]
__device__ ull g_keys[NB * NQ];

__device__ __forceinline__ unsigned f2ord(float f) {
    unsigned u = __float_as_uint(f);
    return (u & 0x80000000u) ? ~u : (u | 0x80000000u);
}
__device__ __forceinline__ float ord2f(unsigned u) {
    return (u & 0x80000000u) ? __uint_as_float(u & 0x7FFFFFFFu)
                             : __uint_as_float(~u);
}

// ---------------------------------------------------------------------------
// Kernel 1: one warp per (b,q) row — max+argmax over 80 classes, sigmoid, mask.
// Grid = 80000 warps => full chip occupancy, DRAM-saturating streaming read.
// ---------------------------------------------------------------------------
__global__ __launch_bounds__(T1)
void score_kernel(const float* __restrict__ logits)
{
    const int wid  = threadIdx.x >> 5;
    const int lane = threadIdx.x & 31;
    const int g    = blockIdx.x * (T1 / 32) + wid;   // global row id, < 80000
    const int b    = g / NQ;
    const int q    = g - b * NQ;

    const float* row = logits + (size_t)g * NC;
    // 3 coalesced row loads in flight before any use
    float v0 = row[lane];
    float v1 = row[lane + 32];
    float v2 = (lane < 16) ? row[lane + 64] : -3.402823466e38f;

    float v = v0; int ci = lane;
    if (v1 > v) { v = v1; ci = lane + 32; }
    if (v2 > v) { v = v2; ci = lane + 64; }
    #pragma unroll
    for (int off = 16; off; off >>= 1) {
        float ov = __shfl_down_sync(0xffffffffu, v,  off);
        int   oi = __shfl_down_sync(0xffffffffu, ci, off);
        if (ov > v || (ov == v && oi < ci)) { v = ov; ci = oi; }
    }
    if (lane == 0) {
        float s  = 1.0f / (1.0f + expf(-v));       // sigmoid monotone => max/argmax commute
        float ms = (s > 0.05f) ? s : -1.0f;
        g_keys[g] = ((ull)f2ord(ms) << 32)
                  | ((ull)(1023 - q) << 10)
                  | (unsigned)ci;
    }
}

// ---------------------------------------------------------------------------
// Kernel 2: per-batch bitonic sort (descending) of 1024 keys, emit top-300.
// Warp owns a contiguous 64-element region => stages with j<=32 use __syncwarp.
// ---------------------------------------------------------------------------
__global__ __launch_bounds__(T2)
void sort_emit_kernel(const float* __restrict__ pboxes,
                      const float* __restrict__ tsizes,
                      float* __restrict__ out)
{
    __shared__ ull keys[NPAD];

    const int b    = blockIdx.x;
    const int tid  = threadIdx.x;
    const int lane = tid & 31;
    const int base = (tid >> 5) * 64;     // warp-local 64-element region

    // load (padding = minimal key)
    #pragma unroll
    for (int i = tid; i < NPAD; i += T2)
        keys[i] = (i < NQ) ? g_keys[b * NQ + i] : 0ULL;
    __syncthreads();

    // warp-local steps for j in [jstart..1] within this warp's 64-elem region
    auto warp_steps = [&](int k, int jstart) {
        for (int j = jstart; j > 0; j >>= 1) {
            int i = base + (((lane & ~(j - 1)) << 1) | (lane & (j - 1)));
            int l = i | j;
            bool up = ((i & k) == 0);
            ull a = keys[i], c = keys[l];
            if (up ? (a < c) : (a > c)) { keys[i] = c; keys[l] = a; }
            __syncwarp();
        }
    };

    // k = 2..64: entirely warp-local
    #pragma unroll
    for (int k = 2; k <= 64; k <<= 1) warp_steps(k, k >> 1);
    __syncthreads();

    // k = 128..1024: cross-warp stages (j>=64) then warp-local tail
    #pragma unroll
    for (int k = 128; k <= NPAD; k <<= 1) {
        for (int j = k >> 1; j >= 64; j >>= 1) {
            int i = ((tid & ~(j - 1)) << 1) | (tid & (j - 1));
            int l = i | j;
            bool up = ((i & k) == 0);
            ull a = keys[i], c = keys[l];
            if (up ? (a < c) : (a > c)) { keys[i] = c; keys[l] = a; }
            __syncthreads();
        }
        warp_steps(k, 32);
        __syncthreads();
    }

    // emit top-300
    const float img_h = tsizes[b * 2 + 0];
    const float img_w = tsizes[b * 2 + 1];
    if (tid < TOPK) {
        ull key     = keys[tid];
        float s     = ord2f((unsigned)(key >> 32));
        int   q     = 1023 - (int)((key >> 10) & 0x3FFu);
        int   label = (int)(key & 0x3FFu);
        bool  valid = s > 0.05f;

        int o = b * TOPK + tid;
        out[o]             = valid ? s : 0.0f;
        out[NB * TOPK + o] = valid ? (float)label : -1.0f;

        float4 r = make_float4(0.f, 0.f, 0.f, 0.f);
        if (valid) {
            float4 pb = *(const float4*)(pboxes + ((size_t)b * NQ + q) * 4);
            r.x = (pb.x - 0.5f * pb.z) * img_w;
            r.y = (pb.y - 0.5f * pb.w) * img_h;
            r.z = (pb.x + 0.5f * pb.z) * img_w;
            r.w = (pb.y + 0.5f * pb.w) * img_h;
        }
        *(float4*)(out + 2 * NB * TOPK + (size_t)o * 4) = r;
    }
}

extern "C" void kernel_launch(void* const* d_in, const int* in_sizes, int n_in,
                              void* d_out, int out_size) {
    const float* logits = (const float*)d_in[0];  // (256,1000,80)
    const float* boxes  = (const float*)d_in[1];  // (256,1000,4)
    const float* tsz    = (const float*)d_in[2];  // (256,2)
    float* out = (float*)d_out;

    score_kernel<<<NB * NQ / (T1 / 32), T1>>>(logits);          // 10000 blocks
    sort_emit_kernel<<<NB, T2>>>(boxes, tsz, out);
}

// round 3
// speedup vs baseline: 1.6986x; 1.6986x over previous
#include <cuda_runtime.h>
#include <cstdint>
#include <cfloat>

#define NB 256
#define NQ 1000
#define NC 80
#define TOPK 300
#define NPAD 1024
#define T1 512          // kernel-1 block: 16 warps x 4 rows = 64 rows/CTA
#define T2 512          // kernel-2 block
#define ROWS_PER_WARP 4

typedef unsigned long long ull;

// per-(batch,query) packed keys: [ordered score 32b | (1023-q) 10b | label 10b]
__device__ ull g_keys[NB * NQ];

__device__ __forceinline__ unsigned f2ord(float f) {
    unsigned u = __float_as_uint(f);
    return (u & 0x80000000u) ? ~u : (u | 0x80000000u);
}
__device__ __forceinline__ float ord2f(unsigned u) {
    return (u & 0x80000000u) ? __uint_as_float(u & 0x7FFFFFFFu)
                             : __uint_as_float(~u);
}

// ---------------------------------------------------------------------------
// Kernel 1: each warp handles 4 consecutive rows; all 12 row-loads issued
// before any reduction => 4x memory-level parallelism per warp.
// ---------------------------------------------------------------------------
__global__ __launch_bounds__(T1)
void score_kernel(const float* __restrict__ logits)
{
    const int wid  = threadIdx.x >> 5;
    const int lane = threadIdx.x & 31;
    const int g0   = (blockIdx.x * (T1 / 32) + wid) * ROWS_PER_WARP;

    const float* base = logits + (size_t)g0 * NC;

    // ---- issue all loads up front (streaming; no reuse) ----
    float a0[ROWS_PER_WARP], a1[ROWS_PER_WARP], a2[ROWS_PER_WARP];
    #pragma unroll
    for (int r = 0; r < ROWS_PER_WARP; r++) {
        const float* row = base + r * NC;
        a0[r] = __ldcs(row + lane);
        a1[r] = __ldcs(row + lane + 32);
        a2[r] = (lane < 16) ? __ldcs(row + lane + 64) : -FLT_MAX;
    }

    // ---- per-row max/argmax, first-index tie-break ----
    ull kk[ROWS_PER_WARP];
    #pragma unroll
    for (int r = 0; r < ROWS_PER_WARP; r++) {
        float v = a0[r]; int ci = lane;
        if (a1[r] > v) { v = a1[r]; ci = lane + 32; }
        if (a2[r] > v) { v = a2[r]; ci = lane + 64; }
        #pragma unroll
        for (int off = 16; off; off >>= 1) {
            float ov = __shfl_down_sync(0xffffffffu, v,  off);
            int   oi = __shfl_down_sync(0xffffffffu, ci, off);
            if (ov > v || (ov == v && oi < ci)) { v = ov; ci = oi; }
        }
        int g = g0 + r;
        int q = g % NQ;
        float s  = 1.0f / (1.0f + expf(-v));   // sigmoid monotone
        float ms = (s > 0.05f) ? s : -1.0f;
        kk[r] = ((ull)f2ord(ms) << 32) | ((ull)(1023 - q) << 10) | (unsigned)ci;
    }

    if (lane == 0) {   // 2 x 16B contiguous stores
        ulonglong2* dst = (ulonglong2*)(g_keys + g0);
        dst[0] = make_ulonglong2(kk[0], kk[1]);
        dst[1] = make_ulonglong2(kk[2], kk[3]);
    }
}

// ---------------------------------------------------------------------------
// Kernel 2: TWO batches per CTA. Each thread does one compare-exchange per
// batch per stage => 2x ILP between barriers; barrier cost amortized.
// ---------------------------------------------------------------------------
__global__ __launch_bounds__(T2)
void sort_emit_kernel(const float* __restrict__ pboxes,
                      const float* __restrict__ tsizes,
                      float* __restrict__ out)
{
    __shared__ ull keys[2][NPAD];

    const int b0   = blockIdx.x * 2;              // batches b0, b0+1
    const int tid  = threadIdx.x;
    const int lane = tid & 31;
    const int base = (tid >> 5) * 64;             // warp-local 64-elem region

    #pragma unroll
    for (int i = tid; i < NPAD; i += T2) {
        keys[0][i] = (i < NQ) ? g_keys[ b0      * NQ + i] : 0ULL;
        keys[1][i] = (i < NQ) ? g_keys[(b0 + 1) * NQ + i] : 0ULL;
    }
    __syncthreads();

    // one CE position, applied to both batches
    auto ce2 = [&](int i, int l, int k) {
        bool up = ((i & k) == 0);
        ull a0 = keys[0][i], c0 = keys[0][l];
        ull a1 = keys[1][i], c1 = keys[1][l];
        if (up ? (a0 < c0) : (a0 > c0)) { keys[0][i] = c0; keys[0][l] = a0; }
        if (up ? (a1 < c1) : (a1 > c1)) { keys[1][i] = c1; keys[1][l] = a1; }
    };

    auto warp_steps = [&](int k, int jstart) {
        for (int j = jstart; j > 0; j >>= 1) {
            int i = base + (((lane & ~(j - 1)) << 1) | (lane & (j - 1)));
            ce2(i, i | j, k);
            __syncwarp();
        }
    };

    #pragma unroll
    for (int k = 2; k <= 64; k <<= 1) warp_steps(k, k >> 1);
    __syncthreads();

    #pragma unroll
    for (int k = 128; k <= NPAD; k <<= 1) {
        for (int j = k >> 1; j >= 64; j >>= 1) {
            int i = ((tid & ~(j - 1)) << 1) | (tid & (j - 1));
            ce2(i, i | j, k);
            __syncthreads();
        }
        warp_steps(k, 32);
        __syncthreads();
    }

    // ---- emit top-300 for both batches ----
    for (int e = tid; e < 2 * TOPK; e += T2) {
        int bb = e / TOPK;
        int i  = e - bb * TOPK;
        int b  = b0 + bb;
        float img_h = tsizes[b * 2 + 0];
        float img_w = tsizes[b * 2 + 1];

        ull key     = keys[bb][i];
        float s     = ord2f((unsigned)(key >> 32));
        int   q     = 1023 - (int)((key >> 10) & 0x3FFu);
        int   label = (int)(key & 0x3FFu);
        bool  valid = s > 0.05f;

        int o = b * TOPK + i;
        out[o]             = valid ? s : 0.0f;
        out[NB * TOPK + o] = valid ? (float)label : -1.0f;

        float4 r = make_float4(0.f, 0.f, 0.f, 0.f);
        if (valid) {
            float4 pb = *(const float4*)(pboxes + ((size_t)b * NQ + q) * 4);
            r.x = (pb.x - 0.5f * pb.z) * img_w;
            r.y = (pb.y - 0.5f * pb.w) * img_h;
            r.z = (pb.x + 0.5f * pb.z) * img_w;
            r.w = (pb.y + 0.5f * pb.w) * img_h;
        }
        *(float4*)(out + 2 * NB * TOPK + (size_t)o * 4) = r;
    }
}

extern "C" void kernel_launch(void* const* d_in, const int* in_sizes, int n_in,
                              void* d_out, int out_size) {
    const float* logits = (const float*)d_in[0];  // (256,1000,80)
    const float* boxes  = (const float*)d_in[1];  // (256,1000,4)
    const float* tsz    = (const float*)d_in[2];  // (256,2)
    float* out = (float*)d_out;

    // 80000 rows / (16 warps * 4 rows) = 1250 blocks
    score_kernel<<<NB * NQ / ((T1 / 32) * ROWS_PER_WARP), T1>>>(logits);
    sort_emit_kernel<<<NB / 2, T2>>>(boxes, tsz, out);
}

// round 4
// speedup vs baseline: 2.3622x; 1.3906x over previous
#include <cuda_runtime.h>
#include <cstdint>
#include <cfloat>

#define NB 256
#define NQ 1000
#define NC 80
#define TOPK 300
#define NPAD 1024
#define T1 512
#define TILE_ROWS 128          // rows per score-CTA (128*80 floats = 2560 float4)
#define T2 256

typedef unsigned long long ull;

// per-(batch,query) packed keys: [ordered score 32b | (1023-q) 10b | label 10b]
__device__ ull g_keys[NB * NQ];

__device__ __forceinline__ unsigned f2ord(float f) {
    unsigned u = __float_as_uint(f);
    return (u & 0x80000000u) ? ~u : (u | 0x80000000u);
}
__device__ __forceinline__ float ord2f(unsigned u) {
    return (u & 0x80000000u) ? __uint_as_float(u & 0x7FFFFFFFu)
                             : __uint_as_float(~u);
}

// ---------------------------------------------------------------------------
// Kernel 1: tile-streaming max/argmax.
// 5 float4 LDGs per thread issued back-to-back (deep MLP), de-swizzled into
// smem with stride 81 (conflict-free), then 4 threads/row reduce 80 elements.
// ---------------------------------------------------------------------------
__global__ __launch_bounds__(T1)
void score_kernel(const float* __restrict__ logits)
{
    __shared__ float sm[TILE_ROWS * 81];

    const int tid = threadIdx.x;
    const size_t f4base = (size_t)blockIdx.x * (TILE_ROWS * NC / 4);
    const float4* src = (const float4*)logits + f4base;

    // ---- bulk load: all 5 float4s in flight before any store/use ----
    float4 v[5];
    #pragma unroll
    for (int i = 0; i < 5; i++) v[i] = __ldcs(src + tid + T1 * i);

    // ---- de-swizzle into smem (row stride 81 floats => conflict-free) ----
    #pragma unroll
    for (int i = 0; i < 5; i++) {
        int fl = (tid + T1 * i) * 4;          // float index within tile
        int r  = fl / NC;
        int c  = fl - r * NC;                  // 4-aligned, <= 76
        float* d = &sm[r * 81 + c];
        d[0] = v[i].x; d[1] = v[i].y; d[2] = v[i].z; d[3] = v[i].w;
    }
    __syncthreads();

    // ---- reduce: 4 threads per row, 20 elements each ----
    const int r  = tid >> 2;
    const int qt = tid & 3;
    const float* row = &sm[r * 81 + qt * 20];
    float best = row[0]; int bi = 0;
    #pragma unroll
    for (int i = 1; i < 20; i++) {
        float x = row[i];
        if (x > best) { best = x; bi = i; }    // strict > keeps lowest index
    }
    bi += qt * 20;
    // combine the 4 sub-threads (consecutive lanes; higher lane = higher cols,
    // so strict > preserves first-index tie-break)
    #pragma unroll
    for (int off = 2; off; off >>= 1) {
        float ov = __shfl_down_sync(0xffffffffu, best, off);
        int   oi = __shfl_down_sync(0xffffffffu, bi,  off);
        if (ov > best) { best = ov; bi = oi; }
    }

    if (qt == 0) {
        int g  = blockIdx.x * TILE_ROWS + r;
        int b  = g / NQ;
        int qq = g - b * NQ;
        float s  = 1.0f / (1.0f + expf(-best));   // sigmoid monotone
        float ms = (s > 0.05f) ? s : -1.0f;
        g_keys[g] = ((ull)f2ord(ms) << 32) | ((ull)(1023 - qq) << 10) | (unsigned)bi;
    }
}

// ---------------------------------------------------------------------------
// Kernel 2: per-batch bitonic sort of 1024 keys, 256 threads (2 CE/thread).
// Each warp owns a contiguous 128-element region, so every stage with j<=64
// is warp-local (__syncwarp only). Only 9 __syncthreads in the whole sort.
// ---------------------------------------------------------------------------
__global__ __launch_bounds__(T2)
void sort_emit_kernel(const float* __restrict__ pboxes,
                      const float* __restrict__ tsizes,
                      float* __restrict__ out)
{
    __shared__ ull keys[NPAD];

    const int b    = blockIdx.x;
    const int tid  = threadIdx.x;
    const int lane = tid & 31;
    const int w    = tid >> 5;          // 8 warps, warp w owns elems [128w,128w+128)

    #pragma unroll
    for (int i = tid; i < NPAD; i += T2)
        keys[i] = (i < NQ) ? g_keys[b * NQ + i] : 0ULL;
    __syncthreads();

    auto ce = [&](int p, int j, int k) {
        int i = ((p & ~(j - 1)) << 1) | (p & (j - 1));
        int l = i | j;
        bool up = ((i & k) == 0);
        ull a = keys[i], c = keys[l];
        if (up ? (a < c) : (a > c)) { keys[i] = c; keys[l] = a; }
    };

    // k = 2..128: all steps (j<=64) warp-local
    #pragma unroll
    for (int k = 2; k <= 128; k <<= 1) {
        for (int j = k >> 1; j > 0; j >>= 1) {
            ce(64 * w + lane, j, k);
            ce(64 * w + lane + 32, j, k);
            __syncwarp();
        }
    }
    __syncthreads();

    // k = 256..1024: cross-warp steps (j>=128), then warp-local tail
    #pragma unroll
    for (int k = 256; k <= NPAD; k <<= 1) {
        for (int j = k >> 1; j >= 128; j >>= 1) {
            ce(tid, j, k);
            ce(tid + 256, j, k);
            __syncthreads();
        }
        for (int j = 64; j > 0; j >>= 1) {
            ce(64 * w + lane, j, k);
            ce(64 * w + lane + 32, j, k);
            __syncwarp();
        }
        __syncthreads();
    }

    // ---- emit top-300 ----
    const float img_h = tsizes[b * 2 + 0];
    const float img_w = tsizes[b * 2 + 1];
    for (int i = tid; i < TOPK; i += T2) {
        ull key     = keys[i];
        float s     = ord2f((unsigned)(key >> 32));
        int   q     = 1023 - (int)((key >> 10) & 0x3FFu);
        int   label = (int)(key & 0x3FFu);
        bool  valid = s > 0.05f;

        int o = b * TOPK + i;
        out[o]             = valid ? s : 0.0f;
        out[NB * TOPK + o] = valid ? (float)label : -1.0f;

        float4 rr = make_float4(0.f, 0.f, 0.f, 0.f);
        if (valid) {
            float4 pb = *(const float4*)(pboxes + ((size_t)b * NQ + q) * 4);
            rr.x = (pb.x - 0.5f * pb.z) * img_w;
            rr.y = (pb.y - 0.5f * pb.w) * img_h;
            rr.z = (pb.x + 0.5f * pb.z) * img_w;
            rr.w = (pb.y + 0.5f * pb.w) * img_h;
        }
        *(float4*)(out + 2 * NB * TOPK + (size_t)o * 4) = rr;
    }
}

extern "C" void kernel_launch(void* const* d_in, const int* in_sizes, int n_in,
                              void* d_out, int out_size) {
    const float* logits = (const float*)d_in[0];  // (256,1000,80)
    const float* boxes  = (const float*)d_in[1];  // (256,1000,4)
    const float* tsz    = (const float*)d_in[2];  // (256,2)
    float* out = (float*)d_out;

    score_kernel<<<NB * NQ / TILE_ROWS, T1>>>(logits);   // 625 blocks
    sort_emit_kernel<<<NB, T2>>>(boxes, tsz, out);       // 256 blocks
}